// round 13
// baseline (speedup 1.0000x reference)
#include <cuda_runtime.h>
#include <cstdint>

// ---------------------------------------------------------------------------
// Fused IGCNet conv, mma.sync 3xTF32 (mask-split), THIN-WARP edition.
// Block: 256 threads / 8 warps / 128 edges / 8 nodes. Warp w owns the m16
// tile of edges 16w..16w+15 == node w. Occ 4 blocks (51.7KB) = 32 warps/SM.
//   GEMM1: A[16,40] x W1[64,40]^T per warp -> H rows (swizzled smem)
//   GEMM2: H[16,64] x W2[32,64]^T -> C-frags -> warp-internal shfl seg-max
//   node MLP layer1: XIN x W3 via mma (8 cols/warp); layer2 warps 0-1.
// R13: 128->256 threads (half work/thread, 2x warps/SM); XIN stride 64->68
//      (was 8-way bank conflict on node-MLP fragment loads).
// ---------------------------------------------------------------------------

#define NMAX 100000
__device__ float g_buf0[(size_t)NMAX * 32];
__device__ float g_buf1[(size_t)NMAX * 32];

// ---- smem layout (float offsets) ----
// U (9216): phase1 A[128][40](5120)+W1[64][40](@5120,2560); phase2 H[128][72];
//           phase3 W3[64][72](@0,4608)+W4[16][72](@4608,1152)
#define OFF_U     0
#define OFF_W2S   9216     // [32][72]=2304 W2; phase3: hid[16][68]
#define OFF_XIN   11520    // [16][68] rows 0-7 = [x_i(32) | aggr(32)], 8-15 pad
#define OFF_OUTS  12608    // [8][18] = 144
#define OFF_B1    12752
#define OFF_B2    12816
#define OFF_B3    12848
#define OFF_B4    12912
#define SMEM_FLOATS 12928  // 51712 B -> 4 blocks/SM

// mask split: hi = x with low 13 mantissa bits cleared, lo = x - hi (exact).
__device__ __forceinline__ void split_tf(float f, uint32_t& hi, uint32_t& lo) {
    hi = __float_as_uint(f) & 0xFFFFE000u;
    lo = __float_as_uint(f - __uint_as_float(hi));
}
__device__ __forceinline__ void mma8(float* c, const uint32_t* a, const uint32_t* b) {
    asm volatile(
        "mma.sync.aligned.m16n8k8.row.col.f32.tf32.tf32.f32 "
        "{%0,%1,%2,%3}, {%4,%5,%6,%7}, {%8,%9}, {%0,%1,%2,%3};"
        : "+f"(c[0]), "+f"(c[1]), "+f"(c[2]), "+f"(c[3])
        : "r"(a[0]), "r"(a[1]), "r"(a[2]), "r"(a[3]), "r"(b[0]), "r"(b[1]));
}
// swizzle for 40-col tiles (A, W1): cols 0..31 3-bit XOR, cols 32..39 1-bit
__device__ __forceinline__ int swA(int c, int x) {
    return (c < 32) ? (c ^ x) : (32 + ((c - 32) ^ (x & 4)));
}

__global__ void __launch_bounds__(256, 4) conv_kernel(
    const float* __restrict__ h_in, float* __restrict__ h_out,
    const int* __restrict__ src, const float* __restrict__ edge_attr,
    const float* __restrict__ w11, const float* __restrict__ b11,
    const float* __restrict__ w12, const float* __restrict__ b12,
    const float* __restrict__ w21, const float* __restrict__ b21,
    const float* __restrict__ w22, const float* __restrict__ b22)
{
    extern __shared__ float s[];
    const int tid = threadIdx.x;
    const int wid = tid >> 5, l = tid & 31;
    const int n0 = blockIdx.x * 8;

    // ---- stage W1/W2 (swizzled) + biases ----
    for (int i = tid; i < 2560; i += 256) {
        int n = i / 40, k = i - 40 * n;
        s[5120 + n * 40 + swA(k, ((n >> 2) & 7) << 2)] = w11[i];
    }
    for (int i = tid; i < 2048; i += 256) {
        int n = i >> 6, k = i & 63;
        s[OFF_W2S + n * 72 + (k ^ (((n >> 2) & 7) << 2))] = w12[i];
    }
    if (tid < 64) s[OFF_B1 + tid] = b11[tid];
    if (tid < 32) s[OFF_B2 + tid] = b12[tid];
    if (tid < 64) s[OFF_B3 + tid] = b21[tid];
    if (tid < 16) s[OFF_B4 + tid] = b22[tid];

    // ---- gather: A[e][k] stride 40 swizzled; 2 threads per edge ----
    {
        const int e = tid & 127;
        const long long eg = (long long)blockIdx.x * 128 + e;
        const int xa = ((e >> 2) & 7) << 2;
        const int rb = OFF_U + e * 40;
        const int si = src[eg];
        const float4* xr = (const float4*)(h_in + (size_t)si * 32);
        if (tid < 128) {           // x cols 0..15
            #pragma unroll
            for (int j = 0; j < 4; j++)
                *(float4*)&s[rb + ((4 * j) ^ xa)] = xr[j];
        } else {                   // x cols 16..31 + edge_attr
            #pragma unroll
            for (int j = 4; j < 8; j++)
                *(float4*)&s[rb + ((4 * j) ^ xa)] = xr[j];
            const float4* ar = (const float4*)(edge_attr + (size_t)eg * 8);
            #pragma unroll
            for (int j = 0; j < 2; j++)
                *(float4*)&s[rb + 32 + ((4 * j) ^ (xa & 4))] = ar[j];
        }
        if (tid < 64) {  // destination-node features -> XIN[:, 0:32]
            int nd = tid >> 3, q = tid & 7;
            float4 v = *(const float4*)(h_in + (size_t)(n0 + nd) * 32 + q * 4);
            *(float4*)&s[OFF_XIN + nd * 68 + q * 4] = v;
        }
    }
    __syncthreads();   // S1

    const int lr = l >> 2, lc = l & 3;
    const int r0 = 16 * wid + lr, r1 = r0 + 8;
    const int x0 = ((r0 >> 2) & 7) << 2;
    const int x1 = ((r1 >> 2) & 7) << 2;

    // ---- GEMM1: A[16,40] x W1^T -> acc[8][4], 3xTF32 ----
    float acc[8][4];
    #pragma unroll
    for (int nt = 0; nt < 8; nt++)
        #pragma unroll
        for (int q = 0; q < 4; q++) acc[nt][q] = 0.f;

    #pragma unroll
    for (int kc = 0; kc < 5; kc++) {
        const int c0 = 8 * kc + lc, c1 = c0 + 4;
        uint32_t ah[4], al[4];
        split_tf(s[OFF_U + r0 * 40 + swA(c0, x0)], ah[0], al[0]);
        split_tf(s[OFF_U + r1 * 40 + swA(c0, x1)], ah[1], al[1]);
        split_tf(s[OFF_U + r0 * 40 + swA(c1, x0)], ah[2], al[2]);
        split_tf(s[OFF_U + r1 * 40 + swA(c1, x1)], ah[3], al[3]);
        #pragma unroll
        for (int nt = 0; nt < 8; nt++) {
            const int wr = 8 * nt + lr;
            const int xw = ((wr >> 2) & 7) << 2;
            uint32_t bh[2], bl[2];
            split_tf(s[5120 + wr * 40 + swA(c0, xw)], bh[0], bl[0]);
            split_tf(s[5120 + wr * 40 + swA(c1, xw)], bh[1], bl[1]);
            mma8(acc[nt], ah, bh);
            mma8(acc[nt], al, bh);
            mma8(acc[nt], ah, bl);
        }
    }
    __syncthreads();   // S2: A/W1 reads done everywhere; U becomes H[128][72]

    // ---- H = relu(acc + b1) -> swizzled smem (float2 stores) ----
    #pragma unroll
    for (int nt = 0; nt < 8; nt++) {
        const int c0 = 8 * nt + 2 * lc;
        const float bv0 = s[OFF_B1 + c0], bv1 = s[OFF_B1 + c0 + 1];
        float2 v01 = make_float2(fmaxf(acc[nt][0] + bv0, 0.f),
                                 fmaxf(acc[nt][1] + bv1, 0.f));
        float2 v23 = make_float2(fmaxf(acc[nt][2] + bv0, 0.f),
                                 fmaxf(acc[nt][3] + bv1, 0.f));
        *(float2*)&s[OFF_U + r0 * 72 + (c0 ^ x0)] = v01;
        *(float2*)&s[OFF_U + r1 * 72 + (c0 ^ x1)] = v23;
    }
    __syncwarp();   // GEMM2 reads only this warp's own H rows

    // ---- GEMM2: H[16,64] x W2^T -> acc2[4][4], 3xTF32 ----
    float acc2[4][4];
    #pragma unroll
    for (int nt = 0; nt < 4; nt++)
        #pragma unroll
        for (int q = 0; q < 4; q++) acc2[nt][q] = 0.f;

    #pragma unroll
    for (int kc = 0; kc < 8; kc++) {
        const int c0 = 8 * kc + lc, c1 = c0 + 4;
        uint32_t ah[4], al[4];
        split_tf(s[OFF_U + r0 * 72 + (c0 ^ x0)], ah[0], al[0]);
        split_tf(s[OFF_U + r1 * 72 + (c0 ^ x1)], ah[1], al[1]);
        split_tf(s[OFF_U + r0 * 72 + (c1 ^ x0)], ah[2], al[2]);
        split_tf(s[OFF_U + r1 * 72 + (c1 ^ x1)], ah[3], al[3]);
        #pragma unroll
        for (int nt = 0; nt < 4; nt++) {
            const int wr = 8 * nt + lr;
            const int xw = ((wr >> 2) & 7) << 2;
            uint32_t bh[2], bl[2];
            split_tf(s[OFF_W2S + wr * 72 + (c0 ^ xw)], bh[0], bl[0]);
            split_tf(s[OFF_W2S + wr * 72 + (c1 ^ xw)], bh[1], bl[1]);
            mma8(acc2[nt], ah, bh);
            mma8(acc2[nt], al, bh);
            mma8(acc2[nt], ah, bl);
        }
    }

    // ---- segment max via shfl_xor (warp w == node w) ----
    #pragma unroll
    for (int nt = 0; nt < 4; nt++) {
        float m0 = fmaxf(acc2[nt][0], acc2[nt][2]);
        float m1 = fmaxf(acc2[nt][1], acc2[nt][3]);
        #pragma unroll
        for (int off = 4; off <= 16; off <<= 1) {
            m0 = fmaxf(m0, __shfl_xor_sync(0xffffffffu, m0, off));
            m1 = fmaxf(m1, __shfl_xor_sync(0xffffffffu, m1, off));
        }
        if (l < 4) {   // lr==0 lanes hold cols 8nt+2l, +1
            const int c0 = 8 * nt + 2 * l;
            s[OFF_XIN + wid * 68 + 32 + c0]     = fmaxf(m0 + s[OFF_B2 + c0], 0.f);
            s[OFF_XIN + wid * 68 + 32 + c0 + 1] = fmaxf(m1 + s[OFF_B2 + c0 + 1], 0.f);
        }
    }
    __syncthreads();   // S3: H dead everywhere, XIN complete

    // ---- stage W3[64][64] + W4[16][64] row-major swizzled into dead U ----
    for (int i4 = tid; i4 < 1024; i4 += 256) {
        const int h = i4 >> 4, cb = (i4 & 15) * 4;
        float4 v = __ldg((const float4*)(w21 + h * 64 + cb));
        *(float4*)&s[OFF_U + h * 72 + (cb ^ (((h >> 2) & 7) << 2))] = v;
    }
    for (int i4 = tid; i4 < 256; i4 += 256) {
        const int n = i4 >> 4, cb = (i4 & 15) * 4;
        float4 v = __ldg((const float4*)(w22 + n * 64 + cb));
        *(float4*)&s[OFF_U + 4608 + n * 72 + (cb ^ (((n >> 2) & 7) << 2))] = v;
    }
    __syncthreads();   // S4: W3/W4 ready

    // ---- node MLP layer1 via mma: warp w -> output cols 8w..8w+7 ----
    // A = XIN[16,68] (rows 8-15 garbage, row-separable); B = W3 rows.
    {
        float acc3[4] = {0.f, 0.f, 0.f, 0.f};
        #pragma unroll
        for (int kc = 0; kc < 8; kc++) {
            const int c0 = 8 * kc + lc, c1 = c0 + 4;
            uint32_t ah[4], al[4];
            split_tf(s[OFF_XIN + lr * 68 + c0],       ah[0], al[0]);
            split_tf(s[OFF_XIN + (lr + 8) * 68 + c0], ah[1], al[1]);
            split_tf(s[OFF_XIN + lr * 68 + c1],       ah[2], al[2]);
            split_tf(s[OFF_XIN + (lr + 8) * 68 + c1], ah[3], al[3]);
            const int wr = 8 * wid + lr;
            const int xw = ((wr >> 2) & 7) << 2;
            uint32_t bh[2], bl[2];
            split_tf(s[OFF_U + wr * 72 + (c0 ^ xw)], bh[0], bl[0]);
            split_tf(s[OFF_U + wr * 72 + (c1 ^ xw)], bh[1], bl[1]);
            mma8(acc3, ah, bh);
            mma8(acc3, al, bh);
            mma8(acc3, ah, bl);
        }
        // hid = relu(acc3 + b3) -> hid[16][68] at OFF_W2S (rows 0-7 valid)
        const int c0 = 8 * wid + 2 * lc;
        float2 v = make_float2(fmaxf(acc3[0] + s[OFF_B3 + c0], 0.f),
                               fmaxf(acc3[1] + s[OFF_B3 + c0 + 1], 0.f));
        *(float2*)&s[OFF_W2S + lr * 68 + c0] = v;
    }
    __syncthreads();   // S5: hid ready

    // ---- node MLP layer2 via mma: warps 0,1 -> output cols 8w..8w+7 ----
    if (wid < 2) {
        float acc4[4] = {0.f, 0.f, 0.f, 0.f};
        #pragma unroll
        for (int kc = 0; kc < 8; kc++) {
            const int c0 = 8 * kc + lc, c1 = c0 + 4;
            uint32_t ah[4], al[4];
            split_tf(s[OFF_W2S + lr * 68 + c0],       ah[0], al[0]);
            split_tf(s[OFF_W2S + (lr + 8) * 68 + c0], ah[1], al[1]);
            split_tf(s[OFF_W2S + lr * 68 + c1],       ah[2], al[2]);
            split_tf(s[OFF_W2S + (lr + 8) * 68 + c1], ah[3], al[3]);
            const int wr = 8 * wid + lr;
            const int xw = ((wr >> 2) & 7) << 2;
            uint32_t bh[2], bl[2];
            split_tf(s[OFF_U + 4608 + wr * 72 + (c0 ^ xw)], bh[0], bl[0]);
            split_tf(s[OFF_U + 4608 + wr * 72 + (c1 ^ xw)], bh[1], bl[1]);
            mma8(acc4, ah, bh);
            mma8(acc4, al, bh);
            mma8(acc4, ah, bl);
        }
        const int c0 = 8 * wid + 2 * lc;
        float2 v = make_float2(fmaxf(acc4[0] + s[OFF_B4 + c0], 0.f),
                               fmaxf(acc4[1] + s[OFF_B4 + c0 + 1], 0.f));
        *(float2*)&s[OFF_OUTS + lr * 18 + c0] = v;
    }
    __syncthreads();   // S6: out_s ready

    // ---- norm clip + output (threads 0..127: node tid/16, col tid%16) ----
    if (tid < 128) {
        const int nd = tid >> 4, q = tid & 15;
        float v = s[OFF_OUTS + nd * 18 + q];
        float ssq = v * v;
        ssq += __shfl_xor_sync(0xffffffffu, ssq, 1);
        ssq += __shfl_xor_sync(0xffffffffu, ssq, 2);
        ssq += __shfl_xor_sync(0xffffffffu, ssq, 4);
        ssq += __shfl_xor_sync(0xffffffffu, ssq, 8);
        const float sn = sqrtf(ssq);
        if (sn > 1.f) v = v / sn;
        const size_t ng = (size_t)(n0 + nd);
        h_out[ng * 32 + q]      = v;
        h_out[ng * 32 + 16 + q] = s[OFF_XIN + nd * 68 + q];  // x[:, :16]
    }
}

extern "C" void kernel_launch(void* const* d_in, const int* in_sizes, int n_in,
                              void* d_out, int out_size)
{
    const float* x     = (const float*)d_in[0];
    const int*   eidx  = (const int*)d_in[1];     // [2, E] int32
    const float* eattr = (const float*)d_in[2];
    const float* w11 = (const float*)d_in[3];
    const float* b11 = (const float*)d_in[4];
    const float* w12 = (const float*)d_in[5];
    const float* b12 = (const float*)d_in[6];
    const float* w21 = (const float*)d_in[7];
    const float* b21 = (const float*)d_in[8];
    const float* w22 = (const float*)d_in[9];
    const float* b22 = (const float*)d_in[10];

    const int nN = in_sizes[0] / 32;          // 100000
    const int* srcp = eidx;                   // row 0 = src
    const int grid = nN / 8;                  // 12500 blocks (8 nodes each)
    const size_t smem = (size_t)SMEM_FLOATS * sizeof(float);

    cudaFuncSetAttribute(conv_kernel, cudaFuncAttributeMaxDynamicSharedMemorySize, (int)smem);

    float *b0, *b1;
    cudaGetSymbolAddress((void**)&b0, g_buf0);
    cudaGetSymbolAddress((void**)&b1, g_buf1);

    conv_kernel<<<grid, 256, smem>>>(x,  b0, srcp, eattr, w11, b11, w12, b12, w21, b21, w22, b22);
    conv_kernel<<<grid, 256, smem>>>(b0, b1, srcp, eattr, w11, b11, w12, b12, w21, b21, w22, b22);
    conv_kernel<<<grid, 256, smem>>>(b1, (float*)d_out, srcp, eattr, w11, b11, w12, b12, w21, b21, w22, b22);
}

// round 14
// speedup vs baseline: 1.0593x; 1.0593x over previous
#include <cuda_runtime.h>
#include <cuda_bf16.h>
#include <cstdint>

// ---------------------------------------------------------------------------
// Fused IGCNet conv, bf16-PAIR emulated fp32 mma (m16n8k16), thin warps.
// Block: 256 threads / 8 warps / 128 edges / 8 nodes; occ 4 (51.7KB smem).
// Every GEMM operand in smem is a packed u32 (bf16 hi | bf16 lo<<16) of the
// fp32 value. One k16 mma window = 8 logical k (same addressing as tf32 k8).
// Full product via 2 mma per window: A*B + swap16(A)*B.
//   GEMM1: A[16,40] x W1[64,40]^T per warp -> H rows (packed)
//   GEMM2: H[16,64] x W2[32,64]^T -> C-frags -> warp shfl seg-max -> aggr
//   node MLP layer1/layer2 via mma; norm clip; x[:,:16] re-read from h_in.
// R14: tf32 3x-split (3 mma + 2 ALU/elem) -> bf16-pair (2 mma + 0 ALU/elem).
// ---------------------------------------------------------------------------

#define NMAX 100000
__device__ float g_buf0[(size_t)NMAX * 32];
__device__ float g_buf1[(size_t)NMAX * 32];

// ---- smem layout (u32/float offsets) ----
// U (9216): phase1 A[128][40](5120)+W1[64][40](@5120,2560); phase2 H[128][72];
//           phase3 W3[64][72](@0,4608)+W4[16][72](@4608,1152)
#define OFF_U     0
#define OFF_W2S   9216     // [32][72]=2304 W2; phase3: hid[16][68]
#define OFF_XIN   11520    // [16][68] rows 0-7 = [x_i(32) | aggr(32)] packed
#define OFF_OUTS  12608    // [8][18] fp32
#define OFF_B1    12752
#define OFF_B2    12816
#define OFF_B3    12848
#define OFF_B4    12912
#define SMEM_FLOATS 12928  // 51712 B -> 4 blocks/SM

// pack fp32 -> (bf16 hi | bf16 lo<<16); lo = bf16(x - float(hi))
__device__ __forceinline__ uint32_t pack_bf(float x) {
    uint32_t h16 = (uint32_t)__bfloat16_as_ushort(__float2bfloat16_rn(x));
    float hf = __uint_as_float(h16 << 16);
    uint32_t l16 = (uint32_t)__bfloat16_as_ushort(__float2bfloat16_rn(x - hf));
    return h16 | (l16 << 16);
}
__device__ __forceinline__ uint32_t swap16(uint32_t a) {
    return __byte_perm(a, 0, 0x1032);
}
__device__ __forceinline__ void mma16(float* c, const uint32_t* a, const uint32_t* b) {
    asm volatile(
        "mma.sync.aligned.m16n8k16.row.col.f32.bf16.bf16.f32 "
        "{%0,%1,%2,%3}, {%4,%5,%6,%7}, {%8,%9}, {%0,%1,%2,%3};"
        : "+f"(c[0]), "+f"(c[1]), "+f"(c[2]), "+f"(c[3])
        : "r"(a[0]), "r"(a[1]), "r"(a[2]), "r"(a[3]), "r"(b[0]), "r"(b[1]));
}
// swizzle for 40-col tiles (A, W1): cols 0..31 3-bit XOR, cols 32..39 1-bit
__device__ __forceinline__ int swA(int c, int x) {
    return (c < 32) ? (c ^ x) : (32 + ((c - 32) ^ (x & 4)));
}

__global__ void __launch_bounds__(256, 4) conv_kernel(
    const float* __restrict__ h_in, float* __restrict__ h_out,
    const int* __restrict__ src, const float* __restrict__ edge_attr,
    const float* __restrict__ w11, const float* __restrict__ b11,
    const float* __restrict__ w12, const float* __restrict__ b12,
    const float* __restrict__ w21, const float* __restrict__ b21,
    const float* __restrict__ w22, const float* __restrict__ b22)
{
    extern __shared__ float s[];
    uint32_t* su = (uint32_t*)s;
    const int tid = threadIdx.x;
    const int wid = tid >> 5, l = tid & 31;
    const int n0 = blockIdx.x * 8;

    // ---- stage W1/W2 packed (swizzled) + biases (fp32) ----
    for (int i = tid; i < 2560; i += 256) {
        int n = i / 40, k = i - 40 * n;
        su[5120 + n * 40 + swA(k, ((n >> 2) & 7) << 2)] = pack_bf(w11[i]);
    }
    for (int i = tid; i < 2048; i += 256) {
        int n = i >> 6, k = i & 63;
        su[OFF_W2S + n * 72 + (k ^ (((n >> 2) & 7) << 2))] = pack_bf(w12[i]);
    }
    if (tid < 64) s[OFF_B1 + tid] = b11[tid];
    if (tid < 32) s[OFF_B2 + tid] = b12[tid];
    if (tid < 64) s[OFF_B3 + tid] = b21[tid];
    if (tid < 16) s[OFF_B4 + tid] = b22[tid];

    // ---- gather: A[e][k] packed, stride 40 swizzled; 2 threads per edge ----
    {
        const int e = tid & 127;
        const long long eg = (long long)blockIdx.x * 128 + e;
        const int xa = ((e >> 2) & 7) << 2;
        const int rb = OFF_U + e * 40;
        const int si = src[eg];
        const float4* xr = (const float4*)(h_in + (size_t)si * 32);
        if (tid < 128) {           // x cols 0..15
            #pragma unroll
            for (int j = 0; j < 4; j++) {
                float4 v = xr[j];
                uint4 p = make_uint4(pack_bf(v.x), pack_bf(v.y), pack_bf(v.z), pack_bf(v.w));
                *(uint4*)&su[rb + ((4 * j) ^ xa)] = p;
            }
        } else {                   // x cols 16..31 + edge_attr
            #pragma unroll
            for (int j = 4; j < 8; j++) {
                float4 v = xr[j];
                uint4 p = make_uint4(pack_bf(v.x), pack_bf(v.y), pack_bf(v.z), pack_bf(v.w));
                *(uint4*)&su[rb + ((4 * j) ^ xa)] = p;
            }
            const float4* ar = (const float4*)(edge_attr + (size_t)eg * 8);
            #pragma unroll
            for (int j = 0; j < 2; j++) {
                float4 v = ar[j];
                uint4 p = make_uint4(pack_bf(v.x), pack_bf(v.y), pack_bf(v.z), pack_bf(v.w));
                *(uint4*)&su[rb + 32 + ((4 * j) ^ (xa & 4))] = p;
            }
        }
        if (tid < 64) {  // destination-node features -> XIN[:, 0:32] packed
            int nd = tid >> 3, q = tid & 7;
            float4 v = *(const float4*)(h_in + (size_t)(n0 + nd) * 32 + q * 4);
            uint4 p = make_uint4(pack_bf(v.x), pack_bf(v.y), pack_bf(v.z), pack_bf(v.w));
            *(uint4*)&su[OFF_XIN + nd * 68 + q * 4] = p;
        }
    }
    __syncthreads();   // S1

    const int lr = l >> 2, lc = l & 3;
    const int r0 = 16 * wid + lr, r1 = r0 + 8;
    const int x0 = ((r0 >> 2) & 7) << 2;
    const int x1 = ((r1 >> 2) & 7) << 2;

    // ---- GEMM1: A[16,40] x W1^T -> acc[8][4] ----
    float acc[8][4];
    #pragma unroll
    for (int nt = 0; nt < 8; nt++)
        #pragma unroll
        for (int q = 0; q < 4; q++) acc[nt][q] = 0.f;

    #pragma unroll
    for (int kc = 0; kc < 5; kc++) {
        const int c0 = 8 * kc + lc, c1 = c0 + 4;
        uint32_t a[4], ar[4];
        a[0] = su[OFF_U + r0 * 40 + swA(c0, x0)];
        a[1] = su[OFF_U + r1 * 40 + swA(c0, x1)];
        a[2] = su[OFF_U + r0 * 40 + swA(c1, x0)];
        a[3] = su[OFF_U + r1 * 40 + swA(c1, x1)];
        #pragma unroll
        for (int j = 0; j < 4; j++) ar[j] = swap16(a[j]);
        #pragma unroll
        for (int nt = 0; nt < 8; nt++) {
            const int wr = 8 * nt + lr;
            const int xw = ((wr >> 2) & 7) << 2;
            uint32_t b[2];
            b[0] = su[5120 + wr * 40 + swA(c0, xw)];
            b[1] = su[5120 + wr * 40 + swA(c1, xw)];
            mma16(acc[nt], a, b);
            mma16(acc[nt], ar, b);
        }
    }
    __syncthreads();   // S2: A/W1 reads done everywhere; U becomes H[128][72]

    // ---- H = relu(acc + b1) -> packed smem (uint2 stores) ----
    #pragma unroll
    for (int nt = 0; nt < 8; nt++) {
        const int c0 = 8 * nt + 2 * lc;
        const float bv0 = s[OFF_B1 + c0], bv1 = s[OFF_B1 + c0 + 1];
        uint2 v01 = make_uint2(pack_bf(fmaxf(acc[nt][0] + bv0, 0.f)),
                               pack_bf(fmaxf(acc[nt][1] + bv1, 0.f)));
        uint2 v23 = make_uint2(pack_bf(fmaxf(acc[nt][2] + bv0, 0.f)),
                               pack_bf(fmaxf(acc[nt][3] + bv1, 0.f)));
        *(uint2*)&su[OFF_U + r0 * 72 + (c0 ^ x0)] = v01;
        *(uint2*)&su[OFF_U + r1 * 72 + (c0 ^ x1)] = v23;
    }
    __syncwarp();   // GEMM2 reads only this warp's own H rows

    // ---- GEMM2: H[16,64] x W2^T -> acc2[4][4] ----
    float acc2[4][4];
    #pragma unroll
    for (int nt = 0; nt < 4; nt++)
        #pragma unroll
        for (int q = 0; q < 4; q++) acc2[nt][q] = 0.f;

    #pragma unroll
    for (int kc = 0; kc < 8; kc++) {
        const int c0 = 8 * kc + lc, c1 = c0 + 4;
        uint32_t a[4], ar[4];
        a[0] = su[OFF_U + r0 * 72 + (c0 ^ x0)];
        a[1] = su[OFF_U + r1 * 72 + (c0 ^ x1)];
        a[2] = su[OFF_U + r0 * 72 + (c1 ^ x0)];
        a[3] = su[OFF_U + r1 * 72 + (c1 ^ x1)];
        #pragma unroll
        for (int j = 0; j < 4; j++) ar[j] = swap16(a[j]);
        #pragma unroll
        for (int nt = 0; nt < 4; nt++) {
            const int wr = 8 * nt + lr;
            const int xw = ((wr >> 2) & 7) << 2;
            uint32_t b[2];
            b[0] = su[OFF_W2S + wr * 72 + (c0 ^ xw)];
            b[1] = su[OFF_W2S + wr * 72 + (c1 ^ xw)];
            mma16(acc2[nt], a, b);
            mma16(acc2[nt], ar, b);
        }
    }

    // ---- segment max via shfl_xor (warp w == node w) ----
    #pragma unroll
    for (int nt = 0; nt < 4; nt++) {
        float m0 = fmaxf(acc2[nt][0], acc2[nt][2]);
        float m1 = fmaxf(acc2[nt][1], acc2[nt][3]);
        #pragma unroll
        for (int off = 4; off <= 16; off <<= 1) {
            m0 = fmaxf(m0, __shfl_xor_sync(0xffffffffu, m0, off));
            m1 = fmaxf(m1, __shfl_xor_sync(0xffffffffu, m1, off));
        }
        if (l < 4) {   // lr==0 lanes hold cols 8nt+2l, +1
            const int c0 = 8 * nt + 2 * l;
            su[OFF_XIN + wid * 68 + 32 + c0]     = pack_bf(fmaxf(m0 + s[OFF_B2 + c0], 0.f));
            su[OFF_XIN + wid * 68 + 32 + c0 + 1] = pack_bf(fmaxf(m1 + s[OFF_B2 + c0 + 1], 0.f));
        }
    }
    __syncthreads();   // S3: H dead everywhere, XIN complete

    // ---- stage W3[64][64] + W4[16][64] packed swizzled into dead U ----
    for (int i4 = tid; i4 < 1024; i4 += 256) {
        const int h = i4 >> 4, cb = (i4 & 15) * 4;
        float4 v = __ldg((const float4*)(w21 + h * 64 + cb));
        uint4 p = make_uint4(pack_bf(v.x), pack_bf(v.y), pack_bf(v.z), pack_bf(v.w));
        *(uint4*)&su[OFF_U + h * 72 + (cb ^ (((h >> 2) & 7) << 2))] = p;
    }
    for (int i4 = tid; i4 < 256; i4 += 256) {
        const int n = i4 >> 4, cb = (i4 & 15) * 4;
        float4 v = __ldg((const float4*)(w22 + n * 64 + cb));
        uint4 p = make_uint4(pack_bf(v.x), pack_bf(v.y), pack_bf(v.z), pack_bf(v.w));
        *(uint4*)&su[OFF_U + 4608 + n * 72 + (cb ^ (((n >> 2) & 7) << 2))] = p;
    }
    __syncthreads();   // S4: W3/W4 ready

    // ---- node MLP layer1 via mma: warp w -> output cols 8w..8w+7 ----
    {
        float acc3[4] = {0.f, 0.f, 0.f, 0.f};
        #pragma unroll
        for (int kc = 0; kc < 8; kc++) {
            const int c0 = 8 * kc + lc, c1 = c0 + 4;
            uint32_t a[4], ar[4];
            a[0] = su[OFF_XIN + lr * 68 + c0];
            a[1] = su[OFF_XIN + (lr + 8) * 68 + c0];
            a[2] = su[OFF_XIN + lr * 68 + c1];
            a[3] = su[OFF_XIN + (lr + 8) * 68 + c1];
            #pragma unroll
            for (int j = 0; j < 4; j++) ar[j] = swap16(a[j]);
            const int wr = 8 * wid + lr;
            const int xw = ((wr >> 2) & 7) << 2;
            uint32_t b[2];
            b[0] = su[OFF_U + wr * 72 + (c0 ^ xw)];
            b[1] = su[OFF_U + wr * 72 + (c1 ^ xw)];
            mma16(acc3, a, b);
            mma16(acc3, ar, b);
        }
        // hid = relu(acc3 + b3) -> hid[16][68] packed at OFF_W2S (rows 0-7)
        const int c0 = 8 * wid + 2 * lc;
        uint2 v = make_uint2(pack_bf(fmaxf(acc3[0] + s[OFF_B3 + c0], 0.f)),
                             pack_bf(fmaxf(acc3[1] + s[OFF_B3 + c0 + 1], 0.f)));
        *(uint2*)&su[OFF_W2S + lr * 68 + c0] = v;
    }
    __syncthreads();   // S5: hid ready

    // ---- node MLP layer2 via mma: warps 0,1 -> output cols 8w..8w+7 ----
    if (wid < 2) {
        float acc4[4] = {0.f, 0.f, 0.f, 0.f};
        #pragma unroll
        for (int kc = 0; kc < 8; kc++) {
            const int c0 = 8 * kc + lc, c1 = c0 + 4;
            uint32_t a[4], ar[4];
            a[0] = su[OFF_W2S + lr * 68 + c0];
            a[1] = su[OFF_W2S + (lr + 8) * 68 + c0];
            a[2] = su[OFF_W2S + lr * 68 + c1];
            a[3] = su[OFF_W2S + (lr + 8) * 68 + c1];
            #pragma unroll
            for (int j = 0; j < 4; j++) ar[j] = swap16(a[j]);
            const int wr = 8 * wid + lr;
            const int xw = ((wr >> 2) & 7) << 2;
            uint32_t b[2];
            b[0] = su[OFF_U + 4608 + wr * 72 + (c0 ^ xw)];
            b[1] = su[OFF_U + 4608 + wr * 72 + (c1 ^ xw)];
            mma16(acc4, a, b);
            mma16(acc4, ar, b);
        }
        const int c0 = 8 * wid + 2 * lc;
        float2 v = make_float2(fmaxf(acc4[0] + s[OFF_B4 + c0], 0.f),
                               fmaxf(acc4[1] + s[OFF_B4 + c0 + 1], 0.f));
        *(float2*)&s[OFF_OUTS + lr * 18 + c0] = v;
    }
    __syncthreads();   // S6: out_s ready

    // ---- norm clip + output (threads 0..127: node tid/16, col tid%16) ----
    if (tid < 128) {
        const int nd = tid >> 4, q = tid & 15;
        float v = s[OFF_OUTS + nd * 18 + q];
        float ssq = v * v;
        ssq += __shfl_xor_sync(0xffffffffu, ssq, 1);
        ssq += __shfl_xor_sync(0xffffffffu, ssq, 2);
        ssq += __shfl_xor_sync(0xffffffffu, ssq, 4);
        ssq += __shfl_xor_sync(0xffffffffu, ssq, 8);
        const float sn = sqrtf(ssq);
        if (sn > 1.f) v = v / sn;
        const size_t ng = (size_t)(n0 + nd);
        h_out[ng * 32 + q]      = v;
        h_out[ng * 32 + 16 + q] = h_in[ng * 32 + q];  // exact x[:, :16] passthrough
    }
}

extern "C" void kernel_launch(void* const* d_in, const int* in_sizes, int n_in,
                              void* d_out, int out_size)
{
    const float* x     = (const float*)d_in[0];
    const int*   eidx  = (const int*)d_in[1];     // [2, E] int32
    const float* eattr = (const float*)d_in[2];
    const float* w11 = (const float*)d_in[3];
    const float* b11 = (const float*)d_in[4];
    const float* w12 = (const float*)d_in[5];
    const float* b12 = (const float*)d_in[6];
    const float* w21 = (const float*)d_in[7];
    const float* b21 = (const float*)d_in[8];
    const float* w22 = (const float*)d_in[9];
    const float* b22 = (const float*)d_in[10];

    const int nN = in_sizes[0] / 32;          // 100000
    const int* srcp = eidx;                   // row 0 = src
    const int grid = nN / 8;                  // 12500 blocks (8 nodes each)
    const size_t smem = (size_t)SMEM_FLOATS * sizeof(float);

    cudaFuncSetAttribute(conv_kernel, cudaFuncAttributeMaxDynamicSharedMemorySize, (int)smem);

    float *b0, *b1;
    cudaGetSymbolAddress((void**)&b0, g_buf0);
    cudaGetSymbolAddress((void**)&b1, g_buf1);

    conv_kernel<<<grid, 256, smem>>>(x,  b0, srcp, eattr, w11, b11, w12, b12, w21, b21, w22, b22);
    conv_kernel<<<grid, 256, smem>>>(b0, b1, srcp, eattr, w11, b11, w12, b12, w21, b21, w22, b22);
    conv_kernel<<<grid, 256, smem>>>(b1, (float*)d_out, srcp, eattr, w11, b11, w12, b12, w21, b21, w22, b22);
}

// round 15
// speedup vs baseline: 1.3880x; 1.3102x over previous
#include <cuda_runtime.h>
#include <cuda_bf16.h>
#include <cstdint>

// ---------------------------------------------------------------------------
// Fused IGCNet conv, bf16-pair emulated fp32 mma, thin warps, H-in-registers.
// Block: 256 threads / 8 warps / 128 edges / 8 nodes; occ 4 (51.7KB smem).
//   GEMM1: A[16,40] x W1[64,40]^T per warp ((hi,lo) packing, 2 mma/8k)
//   H stays in registers: C-frags -> bias+relu -> value-pair A-frags
//   GEMM2: H[16,64] x W2[32,64]^T (value-pair packing, 3 mma/16k, B-only LDS)
//   -> warp shfl seg-max -> aggr; node MLP via mma; norm clip.
// R15: H smem round-trip eliminated (C-frag == A-frag under value-pair
//      packing); W2 re-staged as value-pair hi/lo; S2+syncwarp removed.
// ---------------------------------------------------------------------------

#define NMAX 100000
__device__ float g_buf0[(size_t)NMAX * 32];
__device__ float g_buf1[(size_t)NMAX * 32];

// ---- smem layout (u32/float offsets) ----
// U (9216): phase1 A[128][40](5120)+W1[64][40](@5120,2560);
//           phase3 W3[64][72](@0,4608)+W4[16][72](@4608,1152)
#define OFF_U     0
#define OFF_W2H   9216     // [32][36] value-pair hi; phase3: hid[16][68]
#define OFF_W2L   10368    // [32][36] value-pair lo
#define OFF_XIN   11520    // [16][68] rows 0-7 = [x_i(32) | aggr(32)] (hi,lo) packed
#define OFF_OUTS  12608    // [8][18] fp32
#define OFF_B1    12752
#define OFF_B2    12816
#define OFF_B3    12848
#define OFF_B4    12912
#define SMEM_FLOATS 12928  // 51712 B -> 4 blocks/SM

// (hi,lo) pack of ONE fp32: u32 = bf16(x) | bf16(x - hi)<<16
__device__ __forceinline__ uint32_t pack_bf(float x) {
    uint32_t h16 = (uint32_t)__bfloat16_as_ushort(__float2bfloat16_rn(x));
    float hf = __uint_as_float(h16 << 16);
    uint32_t l16 = (uint32_t)__bfloat16_as_ushort(__float2bfloat16_rn(x - hf));
    return h16 | (l16 << 16);
}
// value-pair pack of TWO fp32: hi = (bf16(v0), bf16(v1)); lo = residuals
__device__ __forceinline__ void pack2(float v0, float v1, uint32_t& hi, uint32_t& lo) {
    __nv_bfloat162 h = __floats2bfloat162_rn(v0, v1);
    float h0 = __bfloat162float(h.x);
    float h1 = __bfloat162float(h.y);
    __nv_bfloat162 lo2 = __floats2bfloat162_rn(v0 - h0, v1 - h1);
    hi = *(uint32_t*)&h;
    lo = *(uint32_t*)&lo2;
}
__device__ __forceinline__ uint32_t swap16(uint32_t a) {
    return __byte_perm(a, 0, 0x1032);
}
__device__ __forceinline__ void mma16(float* c, const uint32_t* a, const uint32_t* b) {
    asm volatile(
        "mma.sync.aligned.m16n8k16.row.col.f32.bf16.bf16.f32 "
        "{%0,%1,%2,%3}, {%4,%5,%6,%7}, {%8,%9}, {%0,%1,%2,%3};"
        : "+f"(c[0]), "+f"(c[1]), "+f"(c[2]), "+f"(c[3])
        : "r"(a[0]), "r"(a[1]), "r"(a[2]), "r"(a[3]), "r"(b[0]), "r"(b[1]));
}
// swizzle for 40-col tiles (A, W1): cols 0..31 3-bit XOR, cols 32..39 1-bit
__device__ __forceinline__ int swA(int c, int x) {
    return (c < 32) ? (c ^ x) : (32 + ((c - 32) ^ (x & 4)));
}

__global__ void __launch_bounds__(256, 4) conv_kernel(
    const float* __restrict__ h_in, float* __restrict__ h_out,
    const int* __restrict__ src, const float* __restrict__ edge_attr,
    const float* __restrict__ w11, const float* __restrict__ b11,
    const float* __restrict__ w12, const float* __restrict__ b12,
    const float* __restrict__ w21, const float* __restrict__ b21,
    const float* __restrict__ w22, const float* __restrict__ b22)
{
    extern __shared__ float s[];
    uint32_t* su = (uint32_t*)s;
    const int tid = threadIdx.x;
    const int wid = tid >> 5, l = tid & 31;
    const int n0 = blockIdx.x * 8;

    // ---- stage W1 (hi,lo)-packed swizzled; W2 value-pair hi/lo ----
    for (int i = tid; i < 2560; i += 256) {
        int n = i / 40, k = i - 40 * n;
        su[5120 + n * 40 + swA(k, ((n >> 2) & 7) << 2)] = pack_bf(w11[i]);
    }
    for (int i = tid; i < 1024; i += 256) {
        int n = i >> 5, j = i & 31;    // 32 rows x 32 k-pairs
        uint32_t hi, lo;
        pack2(w12[n * 64 + 2 * j], w12[n * 64 + 2 * j + 1], hi, lo);
        su[OFF_W2H + n * 36 + j] = hi;
        su[OFF_W2L + n * 36 + j] = lo;
    }
    if (tid < 64) s[OFF_B1 + tid] = b11[tid];
    if (tid < 32) s[OFF_B2 + tid] = b12[tid];
    if (tid < 64) s[OFF_B3 + tid] = b21[tid];
    if (tid < 16) s[OFF_B4 + tid] = b22[tid];

    // ---- gather: A[e][k] (hi,lo)-packed, stride 40 swizzled; 2 thr/edge ----
    {
        const int e = tid & 127;
        const long long eg = (long long)blockIdx.x * 128 + e;
        const int xa = ((e >> 2) & 7) << 2;
        const int rb = OFF_U + e * 40;
        const int si = src[eg];
        const float4* xr = (const float4*)(h_in + (size_t)si * 32);
        if (tid < 128) {           // x cols 0..15
            #pragma unroll
            for (int j = 0; j < 4; j++) {
                float4 v = xr[j];
                uint4 p = make_uint4(pack_bf(v.x), pack_bf(v.y), pack_bf(v.z), pack_bf(v.w));
                *(uint4*)&su[rb + ((4 * j) ^ xa)] = p;
            }
        } else {                   // x cols 16..31 + edge_attr
            #pragma unroll
            for (int j = 4; j < 8; j++) {
                float4 v = xr[j];
                uint4 p = make_uint4(pack_bf(v.x), pack_bf(v.y), pack_bf(v.z), pack_bf(v.w));
                *(uint4*)&su[rb + ((4 * j) ^ xa)] = p;
            }
            const float4* ar = (const float4*)(edge_attr + (size_t)eg * 8);
            #pragma unroll
            for (int j = 0; j < 2; j++) {
                float4 v = ar[j];
                uint4 p = make_uint4(pack_bf(v.x), pack_bf(v.y), pack_bf(v.z), pack_bf(v.w));
                *(uint4*)&su[rb + 32 + ((4 * j) ^ (xa & 4))] = p;
            }
        }
        if (tid < 64) {  // destination-node features -> XIN[:, 0:32] packed
            int nd = tid >> 3, q = tid & 7;
            float4 v = *(const float4*)(h_in + (size_t)(n0 + nd) * 32 + q * 4);
            uint4 p = make_uint4(pack_bf(v.x), pack_bf(v.y), pack_bf(v.z), pack_bf(v.w));
            *(uint4*)&su[OFF_XIN + nd * 68 + q * 4] = p;
        }
    }
    __syncthreads();   // S1

    const int lr = l >> 2, lc = l & 3;
    const int r0 = 16 * wid + lr, r1 = r0 + 8;
    const int x0 = ((r0 >> 2) & 7) << 2;
    const int x1 = ((r1 >> 2) & 7) << 2;

    // ---- GEMM1: A[16,40] x W1^T -> acc[8][4] ((hi,lo), 2 mma/8k) ----
    float acc[8][4];
    #pragma unroll
    for (int nt = 0; nt < 8; nt++)
        #pragma unroll
        for (int q = 0; q < 4; q++) acc[nt][q] = 0.f;

    #pragma unroll
    for (int kc = 0; kc < 5; kc++) {
        const int c0 = 8 * kc + lc, c1 = c0 + 4;
        uint32_t a[4], ar[4];
        a[0] = su[OFF_U + r0 * 40 + swA(c0, x0)];
        a[1] = su[OFF_U + r1 * 40 + swA(c0, x1)];
        a[2] = su[OFF_U + r0 * 40 + swA(c1, x0)];
        a[3] = su[OFF_U + r1 * 40 + swA(c1, x1)];
        #pragma unroll
        for (int j = 0; j < 4; j++) ar[j] = swap16(a[j]);
        #pragma unroll
        for (int nt = 0; nt < 8; nt++) {
            const int wr = 8 * nt + lr;
            const int xw = ((wr >> 2) & 7) << 2;
            uint32_t b[2];
            b[0] = su[5120 + wr * 40 + swA(c0, xw)];
            b[1] = su[5120 + wr * 40 + swA(c1, xw)];
            mma16(acc[nt], a, b);
            mma16(acc[nt], ar, b);
        }
    }

    // ---- H in registers: bias+relu -> value-pair A-frags for GEMM2 ----
    // C-frag (rows lr/lr+8, cols 2lc,2lc+1 of 8nt tile) == A-frag of the
    // k16 window w2=nt/2 (even nt -> a0/a1, odd nt -> a2/a3).
    uint32_t pAh[8][2], pAl[8][2];
    #pragma unroll
    for (int nt = 0; nt < 8; nt++) {
        const int c0 = 8 * nt + 2 * lc;
        const float bv0 = s[OFF_B1 + c0], bv1 = s[OFF_B1 + c0 + 1];
        float v0 = fmaxf(acc[nt][0] + bv0, 0.f);
        float v1 = fmaxf(acc[nt][1] + bv1, 0.f);
        float v2 = fmaxf(acc[nt][2] + bv0, 0.f);
        float v3 = fmaxf(acc[nt][3] + bv1, 0.f);
        pack2(v0, v1, pAh[nt][0], pAl[nt][0]);
        pack2(v2, v3, pAh[nt][1], pAl[nt][1]);
    }

    // ---- GEMM2: H[16,64] x W2^T (value-pair, 3 mma/16k, B-only LDS) ----
    float acc2[4][4];
    #pragma unroll
    for (int nt = 0; nt < 4; nt++)
        #pragma unroll
        for (int q = 0; q < 4; q++) acc2[nt][q] = 0.f;

    #pragma unroll
    for (int w2 = 0; w2 < 4; w2++) {
        const uint32_t Ah[4] = {pAh[2 * w2][0], pAh[2 * w2][1],
                                pAh[2 * w2 + 1][0], pAh[2 * w2 + 1][1]};
        const uint32_t Al[4] = {pAl[2 * w2][0], pAl[2 * w2][1],
                                pAl[2 * w2 + 1][0], pAl[2 * w2 + 1][1]};
        #pragma unroll
        for (int nt = 0; nt < 4; nt++) {
            const int wr = 8 * nt + lr;
            uint32_t bh[2], bl[2];
            bh[0] = su[OFF_W2H + wr * 36 + 8 * w2 + lc];
            bh[1] = su[OFF_W2H + wr * 36 + 8 * w2 + 4 + lc];
            bl[0] = su[OFF_W2L + wr * 36 + 8 * w2 + lc];
            bl[1] = su[OFF_W2L + wr * 36 + 8 * w2 + 4 + lc];
            mma16(acc2[nt], Ah, bh);
            mma16(acc2[nt], Al, bh);
            mma16(acc2[nt], Ah, bl);
        }
    }

    // ---- segment max via shfl_xor (warp w == node w) ----
    #pragma unroll
    for (int nt = 0; nt < 4; nt++) {
        float m0 = fmaxf(acc2[nt][0], acc2[nt][2]);
        float m1 = fmaxf(acc2[nt][1], acc2[nt][3]);
        #pragma unroll
        for (int off = 4; off <= 16; off <<= 1) {
            m0 = fmaxf(m0, __shfl_xor_sync(0xffffffffu, m0, off));
            m1 = fmaxf(m1, __shfl_xor_sync(0xffffffffu, m1, off));
        }
        if (l < 4) {   // lr==0 lanes hold cols 8nt+2l, +1
            const int c0 = 8 * nt + 2 * l;
            su[OFF_XIN + wid * 68 + 32 + c0]     = pack_bf(fmaxf(m0 + s[OFF_B2 + c0], 0.f));
            su[OFF_XIN + wid * 68 + 32 + c0 + 1] = pack_bf(fmaxf(m1 + s[OFF_B2 + c0 + 1], 0.f));
        }
    }
    __syncthreads();   // S3: GEMM1/2 done everywhere; XIN complete; U dead

    // ---- stage W3[64][64] + W4[16][64] (hi,lo)-packed swizzled into U ----
    for (int i4 = tid; i4 < 1024; i4 += 256) {
        const int h = i4 >> 4, cb = (i4 & 15) * 4;
        float4 v = __ldg((const float4*)(w21 + h * 64 + cb));
        uint4 p = make_uint4(pack_bf(v.x), pack_bf(v.y), pack_bf(v.z), pack_bf(v.w));
        *(uint4*)&su[OFF_U + h * 72 + (cb ^ (((h >> 2) & 7) << 2))] = p;
    }
    for (int i4 = tid; i4 < 256; i4 += 256) {
        const int n = i4 >> 4, cb = (i4 & 15) * 4;
        float4 v = __ldg((const float4*)(w22 + n * 64 + cb));
        uint4 p = make_uint4(pack_bf(v.x), pack_bf(v.y), pack_bf(v.z), pack_bf(v.w));
        *(uint4*)&su[OFF_U + 4608 + n * 72 + (cb ^ (((n >> 2) & 7) << 2))] = p;
    }
    __syncthreads();   // S4: W3/W4 ready

    // ---- node MLP layer1 via mma: warp w -> output cols 8w..8w+7 ----
    {
        float acc3[4] = {0.f, 0.f, 0.f, 0.f};
        #pragma unroll
        for (int kc = 0; kc < 8; kc++) {
            const int c0 = 8 * kc + lc, c1 = c0 + 4;
            uint32_t a[4], ar[4];
            a[0] = su[OFF_XIN + lr * 68 + c0];
            a[1] = su[OFF_XIN + (lr + 8) * 68 + c0];
            a[2] = su[OFF_XIN + lr * 68 + c1];
            a[3] = su[OFF_XIN + (lr + 8) * 68 + c1];
            #pragma unroll
            for (int j = 0; j < 4; j++) ar[j] = swap16(a[j]);
            const int wr = 8 * wid + lr;
            const int xw = ((wr >> 2) & 7) << 2;
            uint32_t b[2];
            b[0] = su[OFF_U + wr * 72 + (c0 ^ xw)];
            b[1] = su[OFF_U + wr * 72 + (c1 ^ xw)];
            mma16(acc3, a, b);
            mma16(acc3, ar, b);
        }
        // hid = relu(acc3 + b3) -> hid[16][68] packed at OFF_W2H (rows 0-7)
        const int c0 = 8 * wid + 2 * lc;
        uint2 v = make_uint2(pack_bf(fmaxf(acc3[0] + s[OFF_B3 + c0], 0.f)),
                             pack_bf(fmaxf(acc3[1] + s[OFF_B3 + c0 + 1], 0.f)));
        *(uint2*)&su[OFF_W2H + lr * 68 + c0] = v;
    }
    __syncthreads();   // S5: hid ready

    // ---- node MLP layer2 via mma: warps 0,1 -> output cols 8w..8w+7 ----
    if (wid < 2) {
        float acc4[4] = {0.f, 0.f, 0.f, 0.f};
        #pragma unroll
        for (int kc = 0; kc < 8; kc++) {
            const int c0 = 8 * kc + lc, c1 = c0 + 4;
            uint32_t a[4], ar[4];
            a[0] = su[OFF_W2H + lr * 68 + c0];
            a[1] = su[OFF_W2H + (lr + 8) * 68 + c0];
            a[2] = su[OFF_W2H + lr * 68 + c1];
            a[3] = su[OFF_W2H + (lr + 8) * 68 + c1];
            #pragma unroll
            for (int j = 0; j < 4; j++) ar[j] = swap16(a[j]);
            const int wr = 8 * wid + lr;
            const int xw = ((wr >> 2) & 7) << 2;
            uint32_t b[2];
            b[0] = su[OFF_U + 4608 + wr * 72 + (c0 ^ xw)];
            b[1] = su[OFF_U + 4608 + wr * 72 + (c1 ^ xw)];
            mma16(acc4, a, b);
            mma16(acc4, ar, b);
        }
        const int c0 = 8 * wid + 2 * lc;
        float2 v = make_float2(fmaxf(acc4[0] + s[OFF_B4 + c0], 0.f),
                               fmaxf(acc4[1] + s[OFF_B4 + c0 + 1], 0.f));
        *(float2*)&s[OFF_OUTS + lr * 18 + c0] = v;
    }
    __syncthreads();   // S6: out_s ready

    // ---- norm clip + output (threads 0..127: node tid/16, col tid%16) ----
    if (tid < 128) {
        const int nd = tid >> 4, q = tid & 15;
        float v = s[OFF_OUTS + nd * 18 + q];
        float ssq = v * v;
        ssq += __shfl_xor_sync(0xffffffffu, ssq, 1);
        ssq += __shfl_xor_sync(0xffffffffu, ssq, 2);
        ssq += __shfl_xor_sync(0xffffffffu, ssq, 4);
        ssq += __shfl_xor_sync(0xffffffffu, ssq, 8);
        const float sn = sqrtf(ssq);
        if (sn > 1.f) v = v / sn;
        const size_t ng = (size_t)(n0 + nd);
        h_out[ng * 32 + q]      = v;
        h_out[ng * 32 + 16 + q] = h_in[ng * 32 + q];  // exact x[:, :16] passthrough
    }
}

extern "C" void kernel_launch(void* const* d_in, const int* in_sizes, int n_in,
                              void* d_out, int out_size)
{
    const float* x     = (const float*)d_in[0];
    const int*   eidx  = (const int*)d_in[1];     // [2, E] int32
    const float* eattr = (const float*)d_in[2];
    const float* w11 = (const float*)d_in[3];
    const float* b11 = (const float*)d_in[4];
    const float* w12 = (const float*)d_in[5];
    const float* b12 = (const float*)d_in[6];
    const float* w21 = (const float*)d_in[7];
    const float* b21 = (const float*)d_in[8];
    const float* w22 = (const float*)d_in[9];
    const float* b22 = (const float*)d_in[10];

    const int nN = in_sizes[0] / 32;          // 100000
    const int* srcp = eidx;                   // row 0 = src
    const int grid = nN / 8;                  // 12500 blocks (8 nodes each)
    const size_t smem = (size_t)SMEM_FLOATS * sizeof(float);

    cudaFuncSetAttribute(conv_kernel, cudaFuncAttributeMaxDynamicSharedMemorySize, (int)smem);

    float *b0, *b1;
    cudaGetSymbolAddress((void**)&b0, g_buf0);
    cudaGetSymbolAddress((void**)&b1, g_buf1);

    conv_kernel<<<grid, 256, smem>>>(x,  b0, srcp, eattr, w11, b11, w12, b12, w21, b21, w22, b22);
    conv_kernel<<<grid, 256, smem>>>(b0, b1, srcp, eattr, w11, b11, w12, b12, w21, b21, w22, b22);
    conv_kernel<<<grid, 256, smem>>>(b1, (float*)d_out, srcp, eattr, w11, b11, w12, b12, w21, b21, w22, b22);
}

// round 16
// speedup vs baseline: 1.8433x; 1.3281x over previous
#include <cuda_runtime.h>
#include <cuda_bf16.h>
#include <cstdint>

// ---------------------------------------------------------------------------
// Fused IGCNet conv, bf16-pair emulated fp32 mma, thin warps, H-in-registers,
// PRE-PACKED fragment-ordered weights (packed once by pack_kernel).
// Block: 256 threads / 8 warps / 128 edges / 8 nodes; occ 4 (44.5KB smem).
//   GEMM1: A[16,40] x W1 ((hi,lo), 2 mma/8k; B = uint2 fragment loads)
//   H in registers -> value-pair A-frags
//   GEMM2: H[16,64] x W2 (value-pair, 3 mma/16k, B-only uint2 loads)
//   -> warp shfl seg-max -> aggr; node MLP via mma; norm clip.
// R16: weight packing hoisted to a one-block pack_kernel into __device__
//      globals in per-lane fragment order; block staging = uint4 memcpy;
//      all weight LDS lose swizzle math and halve in count.
// ---------------------------------------------------------------------------

#define NMAX 100000
__device__ float g_buf0[(size_t)NMAX * 32];
__device__ float g_buf1[(size_t)NMAX * 32];

// pre-packed weights, fragment-ordered (see pack_kernel for exact maps)
__device__ uint32_t g_W1P[2560];
__device__ uint32_t g_W2HP[1024];
__device__ uint32_t g_W2LP[1024];
__device__ uint32_t g_W3P[4096];
__device__ uint32_t g_W4P[1024];

// ---- smem layout (u32/float offsets) ----
#define OFF_A     0        // 5120: A tile [128][40] swizzled; phase3: W3P(4096)@0 + W4P(1024)@4096
#define OFF_W1    5120     // 2560 fragment-ordered
#define OFF_W2H   7680     // 1024; phase3: hid[16][68] (1088 spills into W2L)
#define OFF_W2L   8704     // 1024
#define OFF_XIN   9728     // [16][68] rows 0-7 = [x_i(32) | aggr(32)] (hi,lo) packed
#define OFF_OUTS  10816    // [8][18] fp32
#define OFF_B1    10960
#define OFF_B2    11024
#define OFF_B3    11056
#define OFF_B4    11120
#define SMEM_FLOATS 11136  // 44544 B -> 4 blocks/SM

// (hi,lo) pack of ONE fp32: u32 = bf16(x) | bf16(x - hi)<<16
__device__ __forceinline__ uint32_t pack_bf(float x) {
    uint32_t h16 = (uint32_t)__bfloat16_as_ushort(__float2bfloat16_rn(x));
    float hf = __uint_as_float(h16 << 16);
    uint32_t l16 = (uint32_t)__bfloat16_as_ushort(__float2bfloat16_rn(x - hf));
    return h16 | (l16 << 16);
}
// value-pair pack of TWO fp32: hi = (bf16(v0), bf16(v1)); lo = residuals
__device__ __forceinline__ void pack2(float v0, float v1, uint32_t& hi, uint32_t& lo) {
    __nv_bfloat162 h = __floats2bfloat162_rn(v0, v1);
    float h0 = __bfloat162float(h.x);
    float h1 = __bfloat162float(h.y);
    __nv_bfloat162 lo2 = __floats2bfloat162_rn(v0 - h0, v1 - h1);
    hi = *(uint32_t*)&h;
    lo = *(uint32_t*)&lo2;
}
__device__ __forceinline__ uint32_t swap16(uint32_t a) {
    return __byte_perm(a, 0, 0x1032);
}
__device__ __forceinline__ void mma16(float* c, const uint32_t* a, uint32_t b0, uint32_t b1) {
    asm volatile(
        "mma.sync.aligned.m16n8k16.row.col.f32.bf16.bf16.f32 "
        "{%0,%1,%2,%3}, {%4,%5,%6,%7}, {%8,%9}, {%0,%1,%2,%3};"
        : "+f"(c[0]), "+f"(c[1]), "+f"(c[2]), "+f"(c[3])
        : "r"(a[0]), "r"(a[1]), "r"(a[2]), "r"(a[3]), "r"(b0), "r"(b1));
}
// swizzle for 40-col tiles (A only): cols 0..31 3-bit XOR, cols 32..39 1-bit
__device__ __forceinline__ int swA(int c, int x) {
    return (c < 32) ? (c ^ x) : (32 + ((c - 32) ^ (x & 4)));
}

// ---- one-block weight pack kernel (fragment-ordered) ----
__global__ void pack_kernel(const float* __restrict__ w11, const float* __restrict__ w12,
                            const float* __restrict__ w21, const float* __restrict__ w22)
{
    const int tid = threadIdx.x;
    // W1P: idx = ((nt*5+kc)*32 + l)*2 + i ; val = w11[(8nt+lr)*40 + 8kc+lc+4i]
    for (int idx = tid; idx < 2560; idx += 256) {
        int i = idx & 1, l = (idx >> 1) & 31, rest = idx >> 6;
        int kc = rest % 5, nt = rest / 5;
        int lr = l >> 2, lc = l & 3;
        g_W1P[idx] = pack_bf(w11[(8 * nt + lr) * 40 + 8 * kc + lc + 4 * i]);
    }
    // W2HP/W2LP: idx = ((nt*4+w2)*32 + l)*2 + i ; k-pair j = 8w2+lc+4i
    for (int idx = tid; idx < 1024; idx += 256) {
        int i = idx & 1, l = (idx >> 1) & 31, rest = idx >> 6;
        int w2 = rest & 3, nt = rest >> 2;
        int lr = l >> 2, lc = l & 3;
        int wr = 8 * nt + lr, j = 8 * w2 + lc + 4 * i;
        uint32_t hi, lo;
        pack2(w12[wr * 64 + 2 * j], w12[wr * 64 + 2 * j + 1], hi, lo);
        g_W2HP[idx] = hi;
        g_W2LP[idx] = lo;
    }
    // W3P: idx = ((wid*8+kc)*32 + l)*2 + i ; val = w21[(8wid+lr)*64 + 8kc+lc+4i]
    for (int idx = tid; idx < 4096; idx += 256) {
        int i = idx & 1, l = (idx >> 1) & 31, rest = idx >> 6;
        int kc = rest & 7, wd = rest >> 3;
        int lr = l >> 2, lc = l & 3;
        g_W3P[idx] = pack_bf(w21[(8 * wd + lr) * 64 + 8 * kc + lc + 4 * i]);
    }
    // W4P: idx = ((wid*8+kc)*32 + l)*2 + i ; val = w22[(8wid+lr)*64 + 8kc+lc+4i]
    for (int idx = tid; idx < 1024; idx += 256) {
        int i = idx & 1, l = (idx >> 1) & 31, rest = idx >> 6;
        int kc = rest & 7, wd = rest >> 3;
        int lr = l >> 2, lc = l & 3;
        g_W4P[idx] = pack_bf(w22[(8 * wd + lr) * 64 + 8 * kc + lc + 4 * i]);
    }
}

__global__ void __launch_bounds__(256, 4) conv_kernel(
    const float* __restrict__ h_in, float* __restrict__ h_out,
    const int* __restrict__ src, const float* __restrict__ edge_attr,
    const float* __restrict__ b11, const float* __restrict__ b12,
    const float* __restrict__ b21, const float* __restrict__ b22)
{
    extern __shared__ float s[];
    uint32_t* su = (uint32_t*)s;
    const int tid = threadIdx.x;
    const int wid = tid >> 5, l = tid & 31;
    const int n0 = blockIdx.x * 8;

    // ---- stage pre-packed W1/W2 (uint4 memcpy) + biases ----
    {
        uint4* dW1 = (uint4*)&su[OFF_W1];
        const uint4* gW1 = (const uint4*)g_W1P;
        for (int i = tid; i < 640; i += 256) dW1[i] = gW1[i];
        uint4* dH = (uint4*)&su[OFF_W2H];
        const uint4* gH = (const uint4*)g_W2HP;
        uint4* dL = (uint4*)&su[OFF_W2L];
        const uint4* gL = (const uint4*)g_W2LP;
        if (tid < 256) { dH[tid] = gH[tid]; dL[tid] = gL[tid]; }
    }
    if (tid < 64) s[OFF_B1 + tid] = b11[tid];
    if (tid < 32) s[OFF_B2 + tid] = b12[tid];
    if (tid < 64) s[OFF_B3 + tid] = b21[tid];
    if (tid < 16) s[OFF_B4 + tid] = b22[tid];

    // ---- gather: A[e][k] (hi,lo)-packed, stride 40 swizzled; 2 thr/edge ----
    {
        const int e = tid & 127;
        const long long eg = (long long)blockIdx.x * 128 + e;
        const int xa = ((e >> 2) & 7) << 2;
        const int rb = OFF_A + e * 40;
        const int si = src[eg];
        const float4* xr = (const float4*)(h_in + (size_t)si * 32);
        if (tid < 128) {           // x cols 0..15
            #pragma unroll
            for (int j = 0; j < 4; j++) {
                float4 v = xr[j];
                uint4 p = make_uint4(pack_bf(v.x), pack_bf(v.y), pack_bf(v.z), pack_bf(v.w));
                *(uint4*)&su[rb + ((4 * j) ^ xa)] = p;
            }
        } else {                   // x cols 16..31 + edge_attr
            #pragma unroll
            for (int j = 4; j < 8; j++) {
                float4 v = xr[j];
                uint4 p = make_uint4(pack_bf(v.x), pack_bf(v.y), pack_bf(v.z), pack_bf(v.w));
                *(uint4*)&su[rb + ((4 * j) ^ xa)] = p;
            }
            const float4* ar = (const float4*)(edge_attr + (size_t)eg * 8);
            #pragma unroll
            for (int j = 0; j < 2; j++) {
                float4 v = ar[j];
                uint4 p = make_uint4(pack_bf(v.x), pack_bf(v.y), pack_bf(v.z), pack_bf(v.w));
                *(uint4*)&su[rb + 32 + ((4 * j) ^ (xa & 4))] = p;
            }
        }
        if (tid < 64) {  // destination-node features -> XIN[:, 0:32] packed
            int nd = tid >> 3, q = tid & 7;
            float4 v = *(const float4*)(h_in + (size_t)(n0 + nd) * 32 + q * 4);
            uint4 p = make_uint4(pack_bf(v.x), pack_bf(v.y), pack_bf(v.z), pack_bf(v.w));
            *(uint4*)&su[OFF_XIN + nd * 68 + q * 4] = p;
        }
    }
    __syncthreads();   // S1

    const int lr = l >> 2, lc = l & 3;
    const int r0 = 16 * wid + lr, r1 = r0 + 8;
    const int x0 = ((r0 >> 2) & 7) << 2;
    const int x1 = ((r1 >> 2) & 7) << 2;

    // ---- GEMM1: A[16,40] x W1 -> acc[8][4] ((hi,lo), 2 mma/8k) ----
    float acc[8][4];
    #pragma unroll
    for (int nt = 0; nt < 8; nt++)
        #pragma unroll
        for (int q = 0; q < 4; q++) acc[nt][q] = 0.f;

    #pragma unroll
    for (int kc = 0; kc < 5; kc++) {
        const int c0 = 8 * kc + lc, c1 = c0 + 4;
        uint32_t a[4], ar[4];
        a[0] = su[OFF_A + r0 * 40 + swA(c0, x0)];
        a[1] = su[OFF_A + r1 * 40 + swA(c0, x1)];
        a[2] = su[OFF_A + r0 * 40 + swA(c1, x0)];
        a[3] = su[OFF_A + r1 * 40 + swA(c1, x1)];
        #pragma unroll
        for (int j = 0; j < 4; j++) ar[j] = swap16(a[j]);
        #pragma unroll
        for (int nt = 0; nt < 8; nt++) {
            const uint2 b = *(const uint2*)&su[OFF_W1 + ((nt * 5 + kc) * 32 + l) * 2];
            mma16(acc[nt], a, b.x, b.y);
            mma16(acc[nt], ar, b.x, b.y);
        }
    }

    // ---- H in registers: bias+relu -> value-pair A-frags for GEMM2 ----
    uint32_t pAh[8][2], pAl[8][2];
    #pragma unroll
    for (int nt = 0; nt < 8; nt++) {
        const int c0 = 8 * nt + 2 * lc;
        const float bv0 = s[OFF_B1 + c0], bv1 = s[OFF_B1 + c0 + 1];
        float v0 = fmaxf(acc[nt][0] + bv0, 0.f);
        float v1 = fmaxf(acc[nt][1] + bv1, 0.f);
        float v2 = fmaxf(acc[nt][2] + bv0, 0.f);
        float v3 = fmaxf(acc[nt][3] + bv1, 0.f);
        pack2(v0, v1, pAh[nt][0], pAl[nt][0]);
        pack2(v2, v3, pAh[nt][1], pAl[nt][1]);
    }

    // ---- GEMM2: H[16,64] x W2 (value-pair, 3 mma/16k, uint2 B loads) ----
    float acc2[4][4];
    #pragma unroll
    for (int nt = 0; nt < 4; nt++)
        #pragma unroll
        for (int q = 0; q < 4; q++) acc2[nt][q] = 0.f;

    #pragma unroll
    for (int w2 = 0; w2 < 4; w2++) {
        const uint32_t Ah[4] = {pAh[2 * w2][0], pAh[2 * w2][1],
                                pAh[2 * w2 + 1][0], pAh[2 * w2 + 1][1]};
        const uint32_t Al[4] = {pAl[2 * w2][0], pAl[2 * w2][1],
                                pAl[2 * w2 + 1][0], pAl[2 * w2 + 1][1]};
        #pragma unroll
        for (int nt = 0; nt < 4; nt++) {
            const int fo = ((nt * 4 + w2) * 32 + l) * 2;
            const uint2 bh = *(const uint2*)&su[OFF_W2H + fo];
            const uint2 bl = *(const uint2*)&su[OFF_W2L + fo];
            mma16(acc2[nt], Ah, bh.x, bh.y);
            mma16(acc2[nt], Al, bh.x, bh.y);
            mma16(acc2[nt], Ah, bl.x, bl.y);
        }
    }

    // ---- segment max via shfl_xor (warp w == node w) ----
    #pragma unroll
    for (int nt = 0; nt < 4; nt++) {
        float m0 = fmaxf(acc2[nt][0], acc2[nt][2]);
        float m1 = fmaxf(acc2[nt][1], acc2[nt][3]);
        #pragma unroll
        for (int off = 4; off <= 16; off <<= 1) {
            m0 = fmaxf(m0, __shfl_xor_sync(0xffffffffu, m0, off));
            m1 = fmaxf(m1, __shfl_xor_sync(0xffffffffu, m1, off));
        }
        if (l < 4) {   // lr==0 lanes hold cols 8nt+2l, +1
            const int c0 = 8 * nt + 2 * l;
            su[OFF_XIN + wid * 68 + 32 + c0]     = pack_bf(fmaxf(m0 + s[OFF_B2 + c0], 0.f));
            su[OFF_XIN + wid * 68 + 32 + c0 + 1] = pack_bf(fmaxf(m1 + s[OFF_B2 + c0 + 1], 0.f));
        }
    }
    __syncthreads();   // S3: GEMM1/2 done everywhere; XIN complete; A dead

    // ---- stage W3P/W4P into dead A region (uint4 memcpy) ----
    {
        uint4* d3 = (uint4*)&su[OFF_A];
        const uint4* g3 = (const uint4*)g_W3P;
        for (int i = tid; i < 1024; i += 256) d3[i] = g3[i];
        uint4* d4 = (uint4*)&su[OFF_A + 4096];
        const uint4* g4 = (const uint4*)g_W4P;
        if (tid < 256) d4[tid] = g4[tid];
    }
    __syncthreads();   // S4: W3/W4 ready

    // ---- node MLP layer1 via mma: warp w -> output cols 8w..8w+7 ----
    {
        float acc3[4] = {0.f, 0.f, 0.f, 0.f};
        #pragma unroll
        for (int kc = 0; kc < 8; kc++) {
            const int c0 = 8 * kc + lc, c1 = c0 + 4;
            uint32_t a[4], ar[4];
            a[0] = su[OFF_XIN + lr * 68 + c0];
            a[1] = su[OFF_XIN + (lr + 8) * 68 + c0];
            a[2] = su[OFF_XIN + lr * 68 + c1];
            a[3] = su[OFF_XIN + (lr + 8) * 68 + c1];
            #pragma unroll
            for (int j = 0; j < 4; j++) ar[j] = swap16(a[j]);
            const uint2 b = *(const uint2*)&su[OFF_A + ((wid * 8 + kc) * 32 + l) * 2];
            mma16(acc3, a, b.x, b.y);
            mma16(acc3, ar, b.x, b.y);
        }
        // hid = relu(acc3 + b3) -> hid[16][68] packed at OFF_W2H (rows 0-7)
        const int c0 = 8 * wid + 2 * lc;
        uint2 v = make_uint2(pack_bf(fmaxf(acc3[0] + s[OFF_B3 + c0], 0.f)),
                             pack_bf(fmaxf(acc3[1] + s[OFF_B3 + c0 + 1], 0.f)));
        *(uint2*)&su[OFF_W2H + lr * 68 + c0] = v;
    }
    __syncthreads();   // S5: hid ready

    // ---- node MLP layer2 via mma: warps 0,1 -> output cols 8w..8w+7 ----
    if (wid < 2) {
        float acc4[4] = {0.f, 0.f, 0.f, 0.f};
        #pragma unroll
        for (int kc = 0; kc < 8; kc++) {
            const int c0 = 8 * kc + lc, c1 = c0 + 4;
            uint32_t a[4], ar[4];
            a[0] = su[OFF_W2H + lr * 68 + c0];
            a[1] = su[OFF_W2H + (lr + 8) * 68 + c0];
            a[2] = su[OFF_W2H + lr * 68 + c1];
            a[3] = su[OFF_W2H + (lr + 8) * 68 + c1];
            #pragma unroll
            for (int j = 0; j < 4; j++) ar[j] = swap16(a[j]);
            const uint2 b = *(const uint2*)&su[OFF_A + 4096 + ((wid * 8 + kc) * 32 + l) * 2];
            mma16(acc4, a, b.x, b.y);
            mma16(acc4, ar, b.x, b.y);
        }
        const int c0 = 8 * wid + 2 * lc;
        float2 v = make_float2(fmaxf(acc4[0] + s[OFF_B4 + c0], 0.f),
                               fmaxf(acc4[1] + s[OFF_B4 + c0 + 1], 0.f));
        *(float2*)&s[OFF_OUTS + lr * 18 + c0] = v;
    }
    __syncthreads();   // S6: out_s ready

    // ---- norm clip + output (threads 0..127: node tid/16, col tid%16) ----
    if (tid < 128) {
        const int nd = tid >> 4, q = tid & 15;
        float v = s[OFF_OUTS + nd * 18 + q];
        float ssq = v * v;
        ssq += __shfl_xor_sync(0xffffffffu, ssq, 1);
        ssq += __shfl_xor_sync(0xffffffffu, ssq, 2);
        ssq += __shfl_xor_sync(0xffffffffu, ssq, 4);
        ssq += __shfl_xor_sync(0xffffffffu, ssq, 8);
        const float sn = sqrtf(ssq);
        if (sn > 1.f) v = v / sn;
        const size_t ng = (size_t)(n0 + nd);
        h_out[ng * 32 + q]      = v;
        h_out[ng * 32 + 16 + q] = h_in[ng * 32 + q];  // exact x[:, :16] passthrough
    }
}

extern "C" void kernel_launch(void* const* d_in, const int* in_sizes, int n_in,
                              void* d_out, int out_size)
{
    const float* x     = (const float*)d_in[0];
    const int*   eidx  = (const int*)d_in[1];     // [2, E] int32
    const float* eattr = (const float*)d_in[2];
    const float* w11 = (const float*)d_in[3];
    const float* b11 = (const float*)d_in[4];
    const float* w12 = (const float*)d_in[5];
    const float* b12 = (const float*)d_in[6];
    const float* w21 = (const float*)d_in[7];
    const float* b21 = (const float*)d_in[8];
    const float* w22 = (const float*)d_in[9];
    const float* b22 = (const float*)d_in[10];

    const int nN = in_sizes[0] / 32;          // 100000
    const int* srcp = eidx;                   // row 0 = src
    const int grid = nN / 8;                  // 12500 blocks (8 nodes each)
    const size_t smem = (size_t)SMEM_FLOATS * sizeof(float);

    cudaFuncSetAttribute(conv_kernel, cudaFuncAttributeMaxDynamicSharedMemorySize, (int)smem);

    float *b0, *b1;
    cudaGetSymbolAddress((void**)&b0, g_buf0);
    cudaGetSymbolAddress((void**)&b1, g_buf1);

    pack_kernel<<<1, 256>>>(w11, w12, w21, w22);
    conv_kernel<<<grid, 256, smem>>>(x,  b0, srcp, eattr, b11, b12, b21, b22);
    conv_kernel<<<grid, 256, smem>>>(b0, b1, srcp, eattr, b11, b12, b21, b22);
    conv_kernel<<<grid, 256, smem>>>(b1, (float*)d_out, srcp, eattr, b11, b12, b21, b22);
}

// round 17
// speedup vs baseline: 1.8910x; 1.0259x over previous
#include <cuda_runtime.h>
#include <cuda_bf16.h>
#include <cstdint>

// ---------------------------------------------------------------------------
// Fused IGCNet conv, bf16-pair emulated fp32 mma, thin warps, H-in-registers,
// pre-packed fragment-ordered weights read DIRECTLY from global (no smem hop).
// Block: 256 threads / 8 warps / 128 edges / 8 nodes; occ 4 (30.5KB smem).
//   GEMM1: A[16,40] x W1 ((hi,lo), 2 mma/8k; B = __ldg uint2 fragments)
//   H in registers -> value-pair A-frags
//   GEMM2: H[16,64] x W2 (value-pair, 3 mma/16k, __ldg B fragments)
//   -> warp shfl seg-max -> aggr; node MLP via mma (__ldg B); norm clip.
// R17: weight smem staging deleted (38KB x 12500 blocks of redundant L2->smem
//      traffic); B-frags load via __ldg from L1-resident globals; 1 less barrier.
// ---------------------------------------------------------------------------

#define NMAX 100000
__device__ float g_buf0[(size_t)NMAX * 32];
__device__ float g_buf1[(size_t)NMAX * 32];

// pre-packed weights, fragment-ordered (see pack_kernel for exact maps)
__device__ uint32_t g_W1P[2560];
__device__ uint32_t g_W2HP[1024];
__device__ uint32_t g_W2LP[1024];
__device__ uint32_t g_W3P[4096];
__device__ uint32_t g_W4P[1024];

// ---- smem layout (u32/float offsets) ----
#define OFF_A     0        // 5120: A tile [128][40] swizzled
#define OFF_XIN   5120     // [16][68] rows 0-7 = [x_i(32)|aggr(32)] (hi,lo) packed
#define OFF_HID   6208     // [16][68] rows 0-7 valid, packed
#define OFF_OUTS  7296     // [8][18] fp32
#define OFF_B1    7440
#define OFF_B2    7504
#define OFF_B3    7536
#define OFF_B4    7600
#define SMEM_FLOATS 7616   // 30464 B (occupancy reg-capped at 4)

// (hi,lo) pack of ONE fp32: u32 = bf16(x) | bf16(x - hi)<<16
__device__ __forceinline__ uint32_t pack_bf(float x) {
    uint32_t h16 = (uint32_t)__bfloat16_as_ushort(__float2bfloat16_rn(x));
    float hf = __uint_as_float(h16 << 16);
    uint32_t l16 = (uint32_t)__bfloat16_as_ushort(__float2bfloat16_rn(x - hf));
    return h16 | (l16 << 16);
}
// value-pair pack of TWO fp32: hi = (bf16(v0), bf16(v1)); lo = residuals
__device__ __forceinline__ void pack2(float v0, float v1, uint32_t& hi, uint32_t& lo) {
    __nv_bfloat162 h = __floats2bfloat162_rn(v0, v1);
    float h0 = __bfloat162float(h.x);
    float h1 = __bfloat162float(h.y);
    __nv_bfloat162 lo2 = __floats2bfloat162_rn(v0 - h0, v1 - h1);
    hi = *(uint32_t*)&h;
    lo = *(uint32_t*)&lo2;
}
__device__ __forceinline__ uint32_t swap16(uint32_t a) {
    return __byte_perm(a, 0, 0x1032);
}
__device__ __forceinline__ void mma16(float* c, const uint32_t* a, uint32_t b0, uint32_t b1) {
    asm volatile(
        "mma.sync.aligned.m16n8k16.row.col.f32.bf16.bf16.f32 "
        "{%0,%1,%2,%3}, {%4,%5,%6,%7}, {%8,%9}, {%0,%1,%2,%3};"
        : "+f"(c[0]), "+f"(c[1]), "+f"(c[2]), "+f"(c[3])
        : "r"(a[0]), "r"(a[1]), "r"(a[2]), "r"(a[3]), "r"(b0), "r"(b1));
}
// swizzle for 40-col tiles (A only): cols 0..31 3-bit XOR, cols 32..39 1-bit
__device__ __forceinline__ int swA(int c, int x) {
    return (c < 32) ? (c ^ x) : (32 + ((c - 32) ^ (x & 4)));
}

// ---- one-block weight pack kernel (fragment-ordered) ----
__global__ void pack_kernel(const float* __restrict__ w11, const float* __restrict__ w12,
                            const float* __restrict__ w21, const float* __restrict__ w22)
{
    const int tid = threadIdx.x;
    for (int idx = tid; idx < 2560; idx += 256) {
        int i = idx & 1, l = (idx >> 1) & 31, rest = idx >> 6;
        int kc = rest % 5, nt = rest / 5;
        int lr = l >> 2, lc = l & 3;
        g_W1P[idx] = pack_bf(w11[(8 * nt + lr) * 40 + 8 * kc + lc + 4 * i]);
    }
    for (int idx = tid; idx < 1024; idx += 256) {
        int i = idx & 1, l = (idx >> 1) & 31, rest = idx >> 6;
        int w2 = rest & 3, nt = rest >> 2;
        int lr = l >> 2, lc = l & 3;
        int wr = 8 * nt + lr, j = 8 * w2 + lc + 4 * i;
        uint32_t hi, lo;
        pack2(w12[wr * 64 + 2 * j], w12[wr * 64 + 2 * j + 1], hi, lo);
        g_W2HP[idx] = hi;
        g_W2LP[idx] = lo;
    }
    for (int idx = tid; idx < 4096; idx += 256) {
        int i = idx & 1, l = (idx >> 1) & 31, rest = idx >> 6;
        int kc = rest & 7, wd = rest >> 3;
        int lr = l >> 2, lc = l & 3;
        g_W3P[idx] = pack_bf(w21[(8 * wd + lr) * 64 + 8 * kc + lc + 4 * i]);
    }
    for (int idx = tid; idx < 1024; idx += 256) {
        int i = idx & 1, l = (idx >> 1) & 31, rest = idx >> 6;
        int kc = rest & 7, wd = rest >> 3;
        int lr = l >> 2, lc = l & 3;
        g_W4P[idx] = pack_bf(w22[(8 * wd + lr) * 64 + 8 * kc + lc + 4 * i]);
    }
}

__global__ void __launch_bounds__(256, 4) conv_kernel(
    const float* __restrict__ h_in, float* __restrict__ h_out,
    const int* __restrict__ src, const float* __restrict__ edge_attr,
    const float* __restrict__ b11, const float* __restrict__ b12,
    const float* __restrict__ b21, const float* __restrict__ b22)
{
    extern __shared__ float s[];
    uint32_t* su = (uint32_t*)s;
    const int tid = threadIdx.x;
    const int wid = tid >> 5, l = tid & 31;
    const int n0 = blockIdx.x * 8;

    if (tid < 64) s[OFF_B1 + tid] = b11[tid];
    if (tid < 32) s[OFF_B2 + tid] = b12[tid];
    if (tid < 64) s[OFF_B3 + tid] = b21[tid];
    if (tid < 16) s[OFF_B4 + tid] = b22[tid];

    // ---- gather: A[e][k] (hi,lo)-packed, stride 40 swizzled; 2 thr/edge ----
    {
        const int e = tid & 127;
        const long long eg = (long long)blockIdx.x * 128 + e;
        const int xa = ((e >> 2) & 7) << 2;
        const int rb = OFF_A + e * 40;
        const int si = src[eg];
        const float4* xr = (const float4*)(h_in + (size_t)si * 32);
        if (tid < 128) {           // x cols 0..15
            #pragma unroll
            for (int j = 0; j < 4; j++) {
                float4 v = xr[j];
                uint4 p = make_uint4(pack_bf(v.x), pack_bf(v.y), pack_bf(v.z), pack_bf(v.w));
                *(uint4*)&su[rb + ((4 * j) ^ xa)] = p;
            }
        } else {                   // x cols 16..31 + edge_attr
            #pragma unroll
            for (int j = 4; j < 8; j++) {
                float4 v = xr[j];
                uint4 p = make_uint4(pack_bf(v.x), pack_bf(v.y), pack_bf(v.z), pack_bf(v.w));
                *(uint4*)&su[rb + ((4 * j) ^ xa)] = p;
            }
            const float4* ar = (const float4*)(edge_attr + (size_t)eg * 8);
            #pragma unroll
            for (int j = 0; j < 2; j++) {
                float4 v = ar[j];
                uint4 p = make_uint4(pack_bf(v.x), pack_bf(v.y), pack_bf(v.z), pack_bf(v.w));
                *(uint4*)&su[rb + 32 + ((4 * j) ^ (xa & 4))] = p;
            }
        }
        if (tid < 64) {  // destination-node features -> XIN[:, 0:32] packed
            int nd = tid >> 3, q = tid & 7;
            float4 v = *(const float4*)(h_in + (size_t)(n0 + nd) * 32 + q * 4);
            uint4 p = make_uint4(pack_bf(v.x), pack_bf(v.y), pack_bf(v.z), pack_bf(v.w));
            *(uint4*)&su[OFF_XIN + nd * 68 + q * 4] = p;
        }
    }
    __syncthreads();   // S1

    const int lr = l >> 2, lc = l & 3;
    const int r0 = 16 * wid + lr, r1 = r0 + 8;
    const int x0 = ((r0 >> 2) & 7) << 2;
    const int x1 = ((r1 >> 2) & 7) << 2;

    // ---- GEMM1: A[16,40] x W1 -> acc[8][4] ((hi,lo), 2 mma/8k) ----
    float acc[8][4];
    #pragma unroll
    for (int nt = 0; nt < 8; nt++)
        #pragma unroll
        for (int q = 0; q < 4; q++) acc[nt][q] = 0.f;

    #pragma unroll
    for (int kc = 0; kc < 5; kc++) {
        const int c0 = 8 * kc + lc, c1 = c0 + 4;
        uint32_t a[4], ar[4];
        a[0] = su[OFF_A + r0 * 40 + swA(c0, x0)];
        a[1] = su[OFF_A + r1 * 40 + swA(c0, x1)];
        a[2] = su[OFF_A + r0 * 40 + swA(c1, x0)];
        a[3] = su[OFF_A + r1 * 40 + swA(c1, x1)];
        #pragma unroll
        for (int j = 0; j < 4; j++) ar[j] = swap16(a[j]);
        #pragma unroll
        for (int nt = 0; nt < 8; nt++) {
            const uint2 b = __ldg((const uint2*)&g_W1P[((nt * 5 + kc) * 32 + l) * 2]);
            mma16(acc[nt], a, b.x, b.y);
            mma16(acc[nt], ar, b.x, b.y);
        }
    }

    // ---- H in registers: bias+relu -> value-pair A-frags for GEMM2 ----
    uint32_t pAh[8][2], pAl[8][2];
    #pragma unroll
    for (int nt = 0; nt < 8; nt++) {
        const int c0 = 8 * nt + 2 * lc;
        const float bv0 = s[OFF_B1 + c0], bv1 = s[OFF_B1 + c0 + 1];
        float v0 = fmaxf(acc[nt][0] + bv0, 0.f);
        float v1 = fmaxf(acc[nt][1] + bv1, 0.f);
        float v2 = fmaxf(acc[nt][2] + bv0, 0.f);
        float v3 = fmaxf(acc[nt][3] + bv1, 0.f);
        pack2(v0, v1, pAh[nt][0], pAl[nt][0]);
        pack2(v2, v3, pAh[nt][1], pAl[nt][1]);
    }

    // ---- GEMM2: H[16,64] x W2 (value-pair, 3 mma/16k, __ldg B) ----
    float acc2[4][4];
    #pragma unroll
    for (int nt = 0; nt < 4; nt++)
        #pragma unroll
        for (int q = 0; q < 4; q++) acc2[nt][q] = 0.f;

    #pragma unroll
    for (int w2 = 0; w2 < 4; w2++) {
        const uint32_t Ah[4] = {pAh[2 * w2][0], pAh[2 * w2][1],
                                pAh[2 * w2 + 1][0], pAh[2 * w2 + 1][1]};
        const uint32_t Al[4] = {pAl[2 * w2][0], pAl[2 * w2][1],
                                pAl[2 * w2 + 1][0], pAl[2 * w2 + 1][1]};
        #pragma unroll
        for (int nt = 0; nt < 4; nt++) {
            const int fo = ((nt * 4 + w2) * 32 + l) * 2;
            const uint2 bh = __ldg((const uint2*)&g_W2HP[fo]);
            const uint2 bl = __ldg((const uint2*)&g_W2LP[fo]);
            mma16(acc2[nt], Ah, bh.x, bh.y);
            mma16(acc2[nt], Al, bh.x, bh.y);
            mma16(acc2[nt], Ah, bl.x, bl.y);
        }
    }

    // ---- segment max via shfl_xor (warp w == node w) ----
    #pragma unroll
    for (int nt = 0; nt < 4; nt++) {
        float m0 = fmaxf(acc2[nt][0], acc2[nt][2]);
        float m1 = fmaxf(acc2[nt][1], acc2[nt][3]);
        #pragma unroll
        for (int off = 4; off <= 16; off <<= 1) {
            m0 = fmaxf(m0, __shfl_xor_sync(0xffffffffu, m0, off));
            m1 = fmaxf(m1, __shfl_xor_sync(0xffffffffu, m1, off));
        }
        if (l < 4) {   // lr==0 lanes hold cols 8nt+2l, +1
            const int c0 = 8 * nt + 2 * l;
            su[OFF_XIN + wid * 68 + 32 + c0]     = pack_bf(fmaxf(m0 + s[OFF_B2 + c0], 0.f));
            su[OFF_XIN + wid * 68 + 32 + c0 + 1] = pack_bf(fmaxf(m1 + s[OFF_B2 + c0 + 1], 0.f));
        }
    }
    __syncthreads();   // S3: XIN complete everywhere

    // ---- node MLP layer1 via mma: warp w -> output cols 8w..8w+7 ----
    {
        float acc3[4] = {0.f, 0.f, 0.f, 0.f};
        #pragma unroll
        for (int kc = 0; kc < 8; kc++) {
            const int c0 = 8 * kc + lc, c1 = c0 + 4;
            uint32_t a[4], ar[4];
            a[0] = su[OFF_XIN + lr * 68 + c0];
            a[1] = su[OFF_XIN + (lr + 8) * 68 + c0];
            a[2] = su[OFF_XIN + lr * 68 + c1];
            a[3] = su[OFF_XIN + (lr + 8) * 68 + c1];
            #pragma unroll
            for (int j = 0; j < 4; j++) ar[j] = swap16(a[j]);
            const uint2 b = __ldg((const uint2*)&g_W3P[((wid * 8 + kc) * 32 + l) * 2]);
            mma16(acc3, a, b.x, b.y);
            mma16(acc3, ar, b.x, b.y);
        }
        // hid = relu(acc3 + b3) -> hid[16][68] packed (rows 0-7 valid)
        const int c0 = 8 * wid + 2 * lc;
        uint2 v = make_uint2(pack_bf(fmaxf(acc3[0] + s[OFF_B3 + c0], 0.f)),
                             pack_bf(fmaxf(acc3[1] + s[OFF_B3 + c0 + 1], 0.f)));
        *(uint2*)&su[OFF_HID + lr * 68 + c0] = v;
    }
    __syncthreads();   // S5: hid ready

    // ---- node MLP layer2 via mma: warps 0,1 -> output cols 8w..8w+7 ----
    if (wid < 2) {
        float acc4[4] = {0.f, 0.f, 0.f, 0.f};
        #pragma unroll
        for (int kc = 0; kc < 8; kc++) {
            const int c0 = 8 * kc + lc, c1 = c0 + 4;
            uint32_t a[4], ar[4];
            a[0] = su[OFF_HID + lr * 68 + c0];
            a[1] = su[OFF_HID + (lr + 8) * 68 + c0];
            a[2] = su[OFF_HID + lr * 68 + c1];
            a[3] = su[OFF_HID + (lr + 8) * 68 + c1];
            #pragma unroll
            for (int j = 0; j < 4; j++) ar[j] = swap16(a[j]);
            const uint2 b = __ldg((const uint2*)&g_W4P[((wid * 8 + kc) * 32 + l) * 2]);
            mma16(acc4, a, b.x, b.y);
            mma16(acc4, ar, b.x, b.y);
        }
        const int c0 = 8 * wid + 2 * lc;
        float2 v = make_float2(fmaxf(acc4[0] + s[OFF_B4 + c0], 0.f),
                               fmaxf(acc4[1] + s[OFF_B4 + c0 + 1], 0.f));
        *(float2*)&s[OFF_OUTS + lr * 18 + c0] = v;
    }
    __syncthreads();   // S6: out_s ready

    // ---- norm clip + output (threads 0..127: node tid/16, col tid%16) ----
    if (tid < 128) {
        const int nd = tid >> 4, q = tid & 15;
        float v = s[OFF_OUTS + nd * 18 + q];
        float ssq = v * v;
        ssq += __shfl_xor_sync(0xffffffffu, ssq, 1);
        ssq += __shfl_xor_sync(0xffffffffu, ssq, 2);
        ssq += __shfl_xor_sync(0xffffffffu, ssq, 4);
        ssq += __shfl_xor_sync(0xffffffffu, ssq, 8);
        const float sn = sqrtf(ssq);
        if (sn > 1.f) v = v / sn;
        const size_t ng = (size_t)(n0 + nd);
        h_out[ng * 32 + q]      = v;
        h_out[ng * 32 + 16 + q] = h_in[ng * 32 + q];  // exact x[:, :16] passthrough
    }
}

extern "C" void kernel_launch(void* const* d_in, const int* in_sizes, int n_in,
                              void* d_out, int out_size)
{
    const float* x     = (const float*)d_in[0];
    const int*   eidx  = (const int*)d_in[1];     // [2, E] int32
    const float* eattr = (const float*)d_in[2];
    const float* w11 = (const float*)d_in[3];
    const float* b11 = (const float*)d_in[4];
    const float* w12 = (const float*)d_in[5];
    const float* b12 = (const float*)d_in[6];
    const float* w21 = (const float*)d_in[7];
    const float* b21 = (const float*)d_in[8];
    const float* w22 = (const float*)d_in[9];
    const float* b22 = (const float*)d_in[10];

    const int nN = in_sizes[0] / 32;          // 100000
    const int* srcp = eidx;                   // row 0 = src
    const int grid = nN / 8;                  // 12500 blocks (8 nodes each)
    const size_t smem = (size_t)SMEM_FLOATS * sizeof(float);

    cudaFuncSetAttribute(conv_kernel, cudaFuncAttributeMaxDynamicSharedMemorySize, (int)smem);

    float *b0, *b1;
    cudaGetSymbolAddress((void**)&b0, g_buf0);
    cudaGetSymbolAddress((void**)&b1, g_buf1);

    pack_kernel<<<1, 256>>>(w11, w12, w21, w22);
    conv_kernel<<<grid, 256, smem>>>(x,  b0, srcp, eattr, b11, b12, b21, b22);
    conv_kernel<<<grid, 256, smem>>>(b0, b1, srcp, eattr, b11, b12, b21, b22);
    conv_kernel<<<grid, 256, smem>>>(b1, (float*)d_out, srcp, eattr, b11, b12, b21, b22);
}